// round 3
// baseline (speedup 1.0000x reference)
#include <cuda_runtime.h>
#include <math.h>

#define Bb   2
#define Tt   2048
#define Dd   2048
#define Hh   16
#define KVh  4
#define HDd  128
#define REP  (Hh / KVh)
#define NROW (Bb * Tt)
#define QW   (Hh * HDd)    // 2048
#define KW   (KVh * HDd)   // 512

// ---- scratch (static device globals; no allocation) ----
__device__ float g_Q[(size_t)NROW * QW];
__device__ float g_K[(size_t)NROW * KW];
__device__ float g_V[(size_t)NROW * KW];
__device__ float g_O[(size_t)NROW * QW];
__device__ float g_cos[Tt * (HDd / 2)];
__device__ float g_sin[Tt * (HDd / 2)];

// ============================================================
// RoPE tables (double precision for accuracy vs jnp fp32 tables)
// ============================================================
__global__ void rope_tables_kernel() {
    int idx = blockIdx.x * blockDim.x + threadIdx.x;
    if (idx >= Tt * (HDd / 2)) return;
    int i = idx % (HDd / 2);
    int t = idx / (HDd / 2);
    double inv = exp(-((double)(2 * i) / (double)HDd) * log(10000.0));
    double a = (double)t * inv;
    g_cos[idx] = (float)cos(a);
    g_sin[idx] = (float)sin(a);
}

// ============================================================
// fp32 SIMT GEMM: C[M,N] = A[M,K] @ B[K,N], all row-major.
// 128x128 block tile, BK=8, 256 threads, 8x8 per thread.
// Assumes M%128==0, N%128==0, K%8==0 (true for all our shapes).
// ============================================================
__global__ __launch_bounds__(256) void gemm128_kernel(
    const float* __restrict__ A, const float* __restrict__ Bm,
    float* __restrict__ C, int M, int N, int K)
{
    __shared__ float As[8][132];   // padded: conflict-free transposed stores
    __shared__ float Bs[8][128];

    const int bx = blockIdx.x, by = blockIdx.y;
    const int tid = threadIdx.x;

    // A load mapping: one float4 per thread per iter
    const int arow = tid >> 1;            // 0..127
    const int acol = (tid & 1) * 4;       // 0 or 4
    // B load mapping
    const int brow = tid >> 5;            // 0..7
    const int bcol = (tid & 31) * 4;      // 0..124

    const float* Ab = A + (size_t)(by * 128) * K;
    const float* Bb2 = Bm + bx * 128;

    const int tr = (tid / 16) * 8;        // 0..120
    const int tc = (tid % 16) * 8;        // 0..120

    float acc[8][8];
#pragma unroll
    for (int i = 0; i < 8; i++)
#pragma unroll
        for (int j = 0; j < 8; j++) acc[i][j] = 0.f;

    for (int k0 = 0; k0 < K; k0 += 8) {
        float4 av = *(const float4*)(Ab + (size_t)arow * K + k0 + acol);
        float4 bv = *(const float4*)(Bb2 + (size_t)(k0 + brow) * N + bcol);
        As[acol + 0][arow] = av.x;
        As[acol + 1][arow] = av.y;
        As[acol + 2][arow] = av.z;
        As[acol + 3][arow] = av.w;
        *(float4*)&Bs[brow][bcol] = bv;
        __syncthreads();

#pragma unroll
        for (int k = 0; k < 8; k++) {
            float a[8], b[8];
            *(float4*)&a[0] = *(float4*)&As[k][tr];
            *(float4*)&a[4] = *(float4*)&As[k][tr + 4];
            *(float4*)&b[0] = *(float4*)&Bs[k][tc];
            *(float4*)&b[4] = *(float4*)&Bs[k][tc + 4];
#pragma unroll
            for (int i = 0; i < 8; i++)
#pragma unroll
                for (int j = 0; j < 8; j++)
                    acc[i][j] = fmaf(a[i], b[j], acc[i][j]);
        }
        __syncthreads();
    }

    float* Cb = C + (size_t)(by * 128 + tr) * N + bx * 128 + tc;
#pragma unroll
    for (int i = 0; i < 8; i++) {
        float4 v0 = make_float4(acc[i][0], acc[i][1], acc[i][2], acc[i][3]);
        float4 v1 = make_float4(acc[i][4], acc[i][5], acc[i][6], acc[i][7]);
        *(float4*)(Cb + (size_t)i * N)     = v0;
        *(float4*)(Cb + (size_t)i * N + 4) = v1;
    }
}

// ============================================================
// In-place RoPE. width = row width (2048 for Q, 512 for K).
// halfw = width/2 pairs per row. Heads are 128-dim blocks.
// ============================================================
__global__ void rope_apply_kernel(float* __restrict__ X, int halfw, int width) {
    int idx = blockIdx.x * blockDim.x + threadIdx.x;
    int total = NROW * halfw;
    if (idx >= total) return;
    int p = idx % halfw;
    int row = idx / halfw;
    int t = row % Tt;
    int i = p & 63;          // pair index within head
    int hh = p >> 6;         // head
    int col = hh * HDd + 2 * i;
    float c = g_cos[t * 64 + i];
    float s = g_sin[t * 64 + i];
    float* ptr = X + (size_t)row * width + col;
    float x1 = ptr[0], x2 = ptr[1];
    ptr[0] = x1 * c - x2 * s;
    ptr[1] = x1 * s + x2 * c;
}

// ============================================================
// Flash attention, fp32, causal, GQA.
// grid.x = T/64 q-tiles, grid.y = B*H. 256 threads (8 warps x 8 rows).
// smem: Qs[64][128] | KVu (K^T 128x65 then V 64x128, union) | Ps[64][64]
// ============================================================
#define SMEM_ATTN ((64 * 128 + 128 * 65 + 64 * 64) * 4)

__global__ __launch_bounds__(256) void attn_kernel() {
    extern __shared__ float sm[];
    float* Qs  = sm;                 // 8192
    float* KVu = Qs + 64 * 128;      // 8320 (max of K^T and V layouts)
    float* Ps  = KVu + 128 * 65;     // 4096

    const int bh = blockIdx.y;
    const int b = bh / Hh;
    const int h = bh % Hh;
    const int kvh = h / REP;
    const int q0 = blockIdx.x * 64;
    const int tid = threadIdx.x, warp = tid >> 5, lane = tid & 31;
    const float scale = 0.08838834764831845f; // 1/sqrt(128)

    // load Q tile
    const float* Qg = g_Q + ((size_t)(b * Tt + q0)) * QW + h * HDd;
    for (int x = tid; x < 64 * 32; x += 256) {
        int r = x >> 5, d4 = (x & 31) << 2;
        *(float4*)&Qs[r * HDd + d4] = *(const float4*)(Qg + (size_t)r * QW + d4);
    }

    float m[8], l[8], o[8][4];
#pragma unroll
    for (int r = 0; r < 8; r++) {
        m[r] = -1e30f; l[r] = 0.f;
        o[r][0] = o[r][1] = o[r][2] = o[r][3] = 0.f;
    }

    const int ntiles = blockIdx.x + 1;
    for (int tile = 0; tile < ntiles; tile++) {
        const int j0 = tile * 64;
        const float* Kg = g_K + ((size_t)(b * Tt + j0)) * KW + kvh * HDd;
        __syncthreads();  // everyone done with V from prev iter
        // load K^T into KVu: KVu[d*65 + j]
        for (int x = tid; x < 64 * 32; x += 256) {
            int j = x >> 5, d4 = (x & 31) << 2;
            float4 kv = *(const float4*)(Kg + (size_t)j * KW + d4);
            KVu[(d4 + 0) * 65 + j] = kv.x;
            KVu[(d4 + 1) * 65 + j] = kv.y;
            KVu[(d4 + 2) * 65 + j] = kv.z;
            KVu[(d4 + 3) * 65 + j] = kv.w;
        }
        __syncthreads();

        // S = Q K^T, online softmax (warp owns rows warp*8..warp*8+7;
        // lane owns cols lane and lane+32)
#pragma unroll 1
        for (int r8 = 0; r8 < 8; r8++) {
            int r = warp * 8 + r8;
            const float* qrow = &Qs[r * HDd];
            float s0 = 0.f, s1 = 0.f;
#pragma unroll 8
            for (int d = 0; d < HDd; d += 4) {
                float4 q = *(const float4*)(qrow + d);
                s0 = fmaf(q.x, KVu[(d + 0) * 65 + lane], s0);
                s0 = fmaf(q.y, KVu[(d + 1) * 65 + lane], s0);
                s0 = fmaf(q.z, KVu[(d + 2) * 65 + lane], s0);
                s0 = fmaf(q.w, KVu[(d + 3) * 65 + lane], s0);
                s1 = fmaf(q.x, KVu[(d + 0) * 65 + lane + 32], s1);
                s1 = fmaf(q.y, KVu[(d + 1) * 65 + lane + 32], s1);
                s1 = fmaf(q.z, KVu[(d + 2) * 65 + lane + 32], s1);
                s1 = fmaf(q.w, KVu[(d + 3) * 65 + lane + 32], s1);
            }
            s0 *= scale; s1 *= scale;
            if (j0 == q0) {   // diagonal tile: causal mask
                if (lane > r)      s0 = -1e30f;
                if (lane + 32 > r) s1 = -1e30f;
            }
            float mx = fmaxf(s0, s1);
#pragma unroll
            for (int off = 16; off; off >>= 1)
                mx = fmaxf(mx, __shfl_xor_sync(0xFFFFFFFFu, mx, off));
            float mn = fmaxf(m[r8], mx);
            float alpha = __expf(m[r8] - mn);
            float p0 = __expf(s0 - mn);
            float p1 = __expf(s1 - mn);
            float ps = p0 + p1;
#pragma unroll
            for (int off = 16; off; off >>= 1)
                ps += __shfl_xor_sync(0xFFFFFFFFu, ps, off);
            l[r8] = l[r8] * alpha + ps;
            m[r8] = mn;
            o[r8][0] *= alpha; o[r8][1] *= alpha;
            o[r8][2] *= alpha; o[r8][3] *= alpha;
            Ps[r * 64 + lane]      = p0;
            Ps[r * 64 + lane + 32] = p1;
        }
        __syncthreads();  // all warps done reading K^T

        // load V into KVu (row-major 64x128)
        const float* Vg = g_V + ((size_t)(b * Tt + j0)) * KW + kvh * HDd;
        for (int x = tid; x < 64 * 32; x += 256) {
            int j = x >> 5, d4 = (x & 31) << 2;
            *(float4*)&KVu[j * HDd + d4] = *(const float4*)(Vg + (size_t)j * KW + d4);
        }
        __syncthreads();

        // O += P V  (lane owns dims lane*4..lane*4+3)
#pragma unroll 1
        for (int r8 = 0; r8 < 8; r8++) {
            int r = warp * 8 + r8;
            float o0 = o[r8][0], o1 = o[r8][1], o2 = o[r8][2], o3 = o[r8][3];
#pragma unroll 4
            for (int c = 0; c < 64; c++) {
                float p = Ps[r * 64 + c];
                float4 v = *(const float4*)&KVu[c * HDd + lane * 4];
                o0 = fmaf(p, v.x, o0);
                o1 = fmaf(p, v.y, o1);
                o2 = fmaf(p, v.z, o2);
                o3 = fmaf(p, v.w, o3);
            }
            o[r8][0] = o0; o[r8][1] = o1; o[r8][2] = o2; o[r8][3] = o3;
        }
    }

    // epilogue: normalize and store to g_O in [b, t, h*HD] layout
    float* Og = g_O + ((size_t)(b * Tt + q0)) * QW + h * HDd;
#pragma unroll
    for (int r8 = 0; r8 < 8; r8++) {
        int r = warp * 8 + r8;
        float inv = 1.f / l[r8];
        float4 v = make_float4(o[r8][0] * inv, o[r8][1] * inv,
                               o[r8][2] * inv, o[r8][3] * inv);
        *(float4*)(Og + (size_t)r * QW + lane * 4) = v;
    }
}

// ============================================================
extern "C" void kernel_launch(void* const* d_in, const int* in_sizes, int n_in,
                              void* d_out, int out_size) {
    (void)in_sizes; (void)n_in; (void)out_size;
    const float* x  = (const float*)d_in[0];
    const float* Wq = (const float*)d_in[1];
    const float* Wk = (const float*)d_in[2];
    const float* Wv = (const float*)d_in[3];
    const float* Wo = (const float*)d_in[4];
    float* out = (float*)d_out;

    float *Qp, *Kp, *Vp, *Op;
    cudaGetSymbolAddress((void**)&Qp, g_Q);
    cudaGetSymbolAddress((void**)&Kp, g_K);
    cudaGetSymbolAddress((void**)&Vp, g_V);
    cudaGetSymbolAddress((void**)&Op, g_O);

    cudaFuncSetAttribute(attn_kernel,
                         cudaFuncAttributeMaxDynamicSharedMemorySize, SMEM_ATTN);

    // 1. RoPE tables
    {
        int total = Tt * (HDd / 2);
        rope_tables_kernel<<<(total + 255) / 256, 256>>>();
    }
    // 2. Projections
    gemm128_kernel<<<dim3(QW / 128, NROW / 128), 256>>>(x, Wq, Qp, NROW, QW, Dd);
    gemm128_kernel<<<dim3(KW / 128, NROW / 128), 256>>>(x, Wk, Kp, NROW, KW, Dd);
    gemm128_kernel<<<dim3(KW / 128, NROW / 128), 256>>>(x, Wv, Vp, NROW, KW, Dd);
    // 3. RoPE on Q and K
    {
        int totalQ = NROW * (QW / 2);
        rope_apply_kernel<<<(totalQ + 255) / 256, 256>>>(Qp, QW / 2, QW);
        int totalK = NROW * (KW / 2);
        rope_apply_kernel<<<(totalK + 255) / 256, 256>>>(Kp, KW / 2, KW);
    }
    // 4. Attention
    attn_kernel<<<dim3(Tt / 64, Bb * Hh), 256, SMEM_ATTN>>>();
    // 5. Output projection
    gemm128_kernel<<<dim3(Dd / 128, NROW / 128), 256>>>(Op, Wo, out, NROW, Dd, Dd);
}

// round 4
// speedup vs baseline: 1.4545x; 1.4545x over previous
#include <cuda_runtime.h>
#include <math.h>

#define Bb   2
#define Tt   2048
#define Dd   2048
#define Hh   16
#define KVh  4
#define HDd  128
#define REP  (Hh / KVh)
#define NROW (Bb * Tt)
#define QW   (Hh * HDd)    // 2048
#define KW   (KVh * HDd)   // 512

// ---- scratch (static device globals; no allocation) ----
__device__ float g_Q[(size_t)NROW * QW];
__device__ float g_K[(size_t)NROW * KW];
__device__ float g_V[(size_t)NROW * KW];
__device__ float g_O[(size_t)NROW * QW];
__device__ float g_cos[Tt * (HDd / 2)];
__device__ float g_sin[Tt * (HDd / 2)];

// ============================================================
// RoPE tables (double precision for accuracy vs jnp fp32 tables)
// ============================================================
__global__ void rope_tables_kernel() {
    int idx = blockIdx.x * blockDim.x + threadIdx.x;
    if (idx >= Tt * (HDd / 2)) return;
    int i = idx % (HDd / 2);
    int t = idx / (HDd / 2);
    double inv = exp(-((double)(2 * i) / (double)HDd) * log(10000.0));
    double a = (double)t * inv;
    g_cos[idx] = (float)cos(a);
    g_sin[idx] = (float)sin(a);
}

// ============================================================
// TF32 tensor-core GEMM: C[M,N] = A[M,K] @ B[K,N], row-major.
// 128x128x32 block tile, 256 threads = 8 warps, warp tile 32x64.
// mma.sync.m16n8k8.tf32, A frags via ldmatrix, double-buffered smem.
// Requires M%128==0, N%128==0, K%32==0.
// ============================================================
#define BM 128
#define BN 128
#define BK 32
#define LDA 36                 // As row stride (floats), conflict-free ldmatrix
#define LDB 132                // Bs row stride (floats)
#define ASZ (BM * LDA)         // 4608
#define BSZ (BK * LDB)         // 4224
#define SMEM_GEMM ((2 * ASZ + 2 * BSZ) * 4)   // 70656 bytes

__device__ __forceinline__ unsigned f2tf32(float x) {
    unsigned r;
    asm("cvt.rna.tf32.f32 %0, %1;" : "=r"(r) : "f"(x));
    return r;
}

__device__ __forceinline__ void ldm_x4(unsigned* a, const unsigned* p) {
    unsigned addr = (unsigned)__cvta_generic_to_shared(p);
    asm volatile("ldmatrix.sync.aligned.m8n8.x4.shared.b16 {%0,%1,%2,%3}, [%4];"
        : "=r"(a[0]), "=r"(a[1]), "=r"(a[2]), "=r"(a[3]) : "r"(addr));
}

__device__ __forceinline__ void mma_tf32(float* c, const unsigned* a,
                                         unsigned b0, unsigned b1) {
    asm volatile(
        "mma.sync.aligned.m16n8k8.row.col.f32.tf32.tf32.f32 "
        "{%0,%1,%2,%3}, {%4,%5,%6,%7}, {%8,%9}, {%0,%1,%2,%3};"
        : "+f"(c[0]), "+f"(c[1]), "+f"(c[2]), "+f"(c[3])
        : "r"(a[0]), "r"(a[1]), "r"(a[2]), "r"(a[3]), "r"(b0), "r"(b1));
}

__global__ __launch_bounds__(256) void gemm_tf32_kernel(
    const float* __restrict__ A, const float* __restrict__ Bm,
    float* __restrict__ C, int M, int N, int K)
{
    extern __shared__ unsigned smem_u[];
    unsigned* As = smem_u;                 // 2 buffers of ASZ
    unsigned* Bs = smem_u + 2 * ASZ;       // 2 buffers of BSZ

    const int bx = blockIdx.x, by = blockIdx.y;
    const int tid = threadIdx.x;
    const int warp = tid >> 5, lane = tid & 31;
    const int wm = warp & 3;               // 0..3 -> M offset wm*32
    const int wn = warp >> 2;              // 0..1 -> N offset wn*64

    // gmem load mappings
    const int ar = tid >> 3;               // 0..31 (A rows, step 32)
    const int ac = (tid & 7) << 2;         // 0..28
    const int br = tid >> 5;               // 0..7  (B rows, step 8)
    const int bc = (tid & 31) << 2;        // 0..124

    const float* Ag = A + (size_t)(by * BM) * K;
    const float* Bg = Bm + bx * BN;

    float acc[2][8][4];
#pragma unroll
    for (int mt = 0; mt < 2; mt++)
#pragma unroll
        for (int nt = 0; nt < 8; nt++)
#pragma unroll
            for (int i = 0; i < 4; i++) acc[mt][nt][i] = 0.f;

    float4 av[4], bv[4];

    // ---- load tile 0 ----
#pragma unroll
    for (int i = 0; i < 4; i++)
        av[i] = *(const float4*)(Ag + (size_t)(ar + 32 * i) * K + ac);
#pragma unroll
    for (int i = 0; i < 4; i++)
        bv[i] = *(const float4*)(Bg + (size_t)(br + 8 * i) * N + bc);
#pragma unroll
    for (int i = 0; i < 4; i++) {
        uint4 u;
        u.x = f2tf32(av[i].x); u.y = f2tf32(av[i].y);
        u.z = f2tf32(av[i].z); u.w = f2tf32(av[i].w);
        *(uint4*)&As[(ar + 32 * i) * LDA + ac] = u;
        uint4 w;
        w.x = f2tf32(bv[i].x); w.y = f2tf32(bv[i].y);
        w.z = f2tf32(bv[i].z); w.w = f2tf32(bv[i].w);
        *(uint4*)&Bs[(br + 8 * i) * LDB + bc] = w;
    }
    __syncthreads();

    int buf = 0;
    for (int k0 = BK; k0 <= K; k0 += BK) {
        // prefetch next tile into regs
        if (k0 < K) {
#pragma unroll
            for (int i = 0; i < 4; i++)
                av[i] = *(const float4*)(Ag + (size_t)(ar + 32 * i) * K + k0 + ac);
#pragma unroll
            for (int i = 0; i < 4; i++)
                bv[i] = *(const float4*)(Bg + (size_t)(k0 + br + 8 * i) * N + bc);
        }

        // ---- compute on current buffer ----
        const unsigned* Ab = As + buf * ASZ;
        const unsigned* Bt = Bs + buf * BSZ;
        const int arow = (lane & 7) + ((lane >> 3) & 1) * 8;
        const int acol = (lane >> 4) << 2;
#pragma unroll
        for (int ks = 0; ks < 4; ks++) {
            unsigned afr[2][4];
#pragma unroll
            for (int mt = 0; mt < 2; mt++) {
                int m0 = wm * 32 + mt * 16;
                ldm_x4(afr[mt], Ab + (m0 + arow) * LDA + ks * 8 + acol);
            }
            const unsigned* Bk = Bt + (ks * 8 + (lane & 3)) * LDB + wn * 64 + (lane >> 2);
#pragma unroll
            for (int nt = 0; nt < 8; nt++) {
                unsigned b0 = Bk[nt * 8];
                unsigned b1 = Bk[nt * 8 + 4 * LDB];
                mma_tf32(acc[0][nt], afr[0], b0, b1);
                mma_tf32(acc[1][nt], afr[1], b0, b1);
            }
        }

        // ---- store prefetched tile into other buffer ----
        if (k0 < K) {
            unsigned* Aw = As + (buf ^ 1) * ASZ;
            unsigned* Bw = Bs + (buf ^ 1) * BSZ;
#pragma unroll
            for (int i = 0; i < 4; i++) {
                uint4 u;
                u.x = f2tf32(av[i].x); u.y = f2tf32(av[i].y);
                u.z = f2tf32(av[i].z); u.w = f2tf32(av[i].w);
                *(uint4*)&Aw[(ar + 32 * i) * LDA + ac] = u;
                uint4 w;
                w.x = f2tf32(bv[i].x); w.y = f2tf32(bv[i].y);
                w.z = f2tf32(bv[i].z); w.w = f2tf32(bv[i].w);
                *(uint4*)&Bw[(br + 8 * i) * LDB + bc] = w;
            }
            __syncthreads();
            buf ^= 1;
        }
    }

    // ---- epilogue ----
    const int g = lane >> 2;
    const int cc = (lane & 3) << 1;
#pragma unroll
    for (int mt = 0; mt < 2; mt++) {
#pragma unroll
        for (int nt = 0; nt < 8; nt++) {
            int row = by * BM + wm * 32 + mt * 16 + g;
            int col = bx * BN + wn * 64 + nt * 8 + cc;
            *(float2*)&C[(size_t)row * N + col] =
                make_float2(acc[mt][nt][0], acc[mt][nt][1]);
            *(float2*)&C[(size_t)(row + 8) * N + col] =
                make_float2(acc[mt][nt][2], acc[mt][nt][3]);
        }
    }
}

// ============================================================
// In-place RoPE. width = row width (2048 for Q, 512 for K).
// ============================================================
__global__ void rope_apply_kernel(float* __restrict__ X, int halfw, int width) {
    int idx = blockIdx.x * blockDim.x + threadIdx.x;
    int total = NROW * halfw;
    if (idx >= total) return;
    int p = idx % halfw;
    int row = idx / halfw;
    int t = row % Tt;
    int i = p & 63;
    int hh = p >> 6;
    int col = hh * HDd + 2 * i;
    float c = g_cos[t * 64 + i];
    float s = g_sin[t * 64 + i];
    float* ptr = X + (size_t)row * width + col;
    float x1 = ptr[0], x2 = ptr[1];
    ptr[0] = x1 * c - x2 * s;
    ptr[1] = x1 * s + x2 * c;
}

// ============================================================
// Flash attention, fp32, causal, GQA (unchanged this round).
// ============================================================
#define SMEM_ATTN ((64 * 128 + 128 * 65 + 64 * 64) * 4)

__global__ __launch_bounds__(256) void attn_kernel() {
    extern __shared__ float sm[];
    float* Qs  = sm;
    float* KVu = Qs + 64 * 128;
    float* Ps  = KVu + 128 * 65;

    const int bh = blockIdx.y;
    const int b = bh / Hh;
    const int h = bh % Hh;
    const int kvh = h / REP;
    const int q0 = blockIdx.x * 64;
    const int tid = threadIdx.x, warp = tid >> 5, lane = tid & 31;
    const float scale = 0.08838834764831845f;

    const float* Qg = g_Q + ((size_t)(b * Tt + q0)) * QW + h * HDd;
    for (int x = tid; x < 64 * 32; x += 256) {
        int r = x >> 5, d4 = (x & 31) << 2;
        *(float4*)&Qs[r * HDd + d4] = *(const float4*)(Qg + (size_t)r * QW + d4);
    }

    float m[8], l[8], o[8][4];
#pragma unroll
    for (int r = 0; r < 8; r++) {
        m[r] = -1e30f; l[r] = 0.f;
        o[r][0] = o[r][1] = o[r][2] = o[r][3] = 0.f;
    }

    const int ntiles = blockIdx.x + 1;
    for (int tile = 0; tile < ntiles; tile++) {
        const int j0 = tile * 64;
        const float* Kg = g_K + ((size_t)(b * Tt + j0)) * KW + kvh * HDd;
        __syncthreads();
        for (int x = tid; x < 64 * 32; x += 256) {
            int j = x >> 5, d4 = (x & 31) << 2;
            float4 kv = *(const float4*)(Kg + (size_t)j * KW + d4);
            KVu[(d4 + 0) * 65 + j] = kv.x;
            KVu[(d4 + 1) * 65 + j] = kv.y;
            KVu[(d4 + 2) * 65 + j] = kv.z;
            KVu[(d4 + 3) * 65 + j] = kv.w;
        }
        __syncthreads();

#pragma unroll 1
        for (int r8 = 0; r8 < 8; r8++) {
            int r = warp * 8 + r8;
            const float* qrow = &Qs[r * HDd];
            float s0 = 0.f, s1 = 0.f;
#pragma unroll 8
            for (int d = 0; d < HDd; d += 4) {
                float4 q = *(const float4*)(qrow + d);
                s0 = fmaf(q.x, KVu[(d + 0) * 65 + lane], s0);
                s0 = fmaf(q.y, KVu[(d + 1) * 65 + lane], s0);
                s0 = fmaf(q.z, KVu[(d + 2) * 65 + lane], s0);
                s0 = fmaf(q.w, KVu[(d + 3) * 65 + lane], s0);
                s1 = fmaf(q.x, KVu[(d + 0) * 65 + lane + 32], s1);
                s1 = fmaf(q.y, KVu[(d + 1) * 65 + lane + 32], s1);
                s1 = fmaf(q.z, KVu[(d + 2) * 65 + lane + 32], s1);
                s1 = fmaf(q.w, KVu[(d + 3) * 65 + lane + 32], s1);
            }
            s0 *= scale; s1 *= scale;
            if (j0 == q0) {
                if (lane > r)      s0 = -1e30f;
                if (lane + 32 > r) s1 = -1e30f;
            }
            float mx = fmaxf(s0, s1);
#pragma unroll
            for (int off = 16; off; off >>= 1)
                mx = fmaxf(mx, __shfl_xor_sync(0xFFFFFFFFu, mx, off));
            float mn = fmaxf(m[r8], mx);
            float alpha = __expf(m[r8] - mn);
            float p0 = __expf(s0 - mn);
            float p1 = __expf(s1 - mn);
            float ps = p0 + p1;
#pragma unroll
            for (int off = 16; off; off >>= 1)
                ps += __shfl_xor_sync(0xFFFFFFFFu, ps, off);
            l[r8] = l[r8] * alpha + ps;
            m[r8] = mn;
            o[r8][0] *= alpha; o[r8][1] *= alpha;
            o[r8][2] *= alpha; o[r8][3] *= alpha;
            Ps[r * 64 + lane]      = p0;
            Ps[r * 64 + lane + 32] = p1;
        }
        __syncthreads();

        const float* Vg = g_V + ((size_t)(b * Tt + j0)) * KW + kvh * HDd;
        for (int x = tid; x < 64 * 32; x += 256) {
            int j = x >> 5, d4 = (x & 31) << 2;
            *(float4*)&KVu[j * HDd + d4] = *(const float4*)(Vg + (size_t)j * KW + d4);
        }
        __syncthreads();

#pragma unroll 1
        for (int r8 = 0; r8 < 8; r8++) {
            int r = warp * 8 + r8;
            float o0 = o[r8][0], o1 = o[r8][1], o2 = o[r8][2], o3 = o[r8][3];
#pragma unroll 4
            for (int c = 0; c < 64; c++) {
                float p = Ps[r * 64 + c];
                float4 v = *(const float4*)&KVu[c * HDd + lane * 4];
                o0 = fmaf(p, v.x, o0);
                o1 = fmaf(p, v.y, o1);
                o2 = fmaf(p, v.z, o2);
                o3 = fmaf(p, v.w, o3);
            }
            o[r8][0] = o0; o[r8][1] = o1; o[r8][2] = o2; o[r8][3] = o3;
        }
    }

    float* Og = g_O + ((size_t)(b * Tt + q0)) * QW + h * HDd;
#pragma unroll
    for (int r8 = 0; r8 < 8; r8++) {
        int r = warp * 8 + r8;
        float inv = 1.f / l[r8];
        float4 v = make_float4(o[r8][0] * inv, o[r8][1] * inv,
                               o[r8][2] * inv, o[r8][3] * inv);
        *(float4*)(Og + (size_t)r * QW + lane * 4) = v;
    }
}

// ============================================================
extern "C" void kernel_launch(void* const* d_in, const int* in_sizes, int n_in,
                              void* d_out, int out_size) {
    (void)in_sizes; (void)n_in; (void)out_size;
    const float* x  = (const float*)d_in[0];
    const float* Wq = (const float*)d_in[1];
    const float* Wk = (const float*)d_in[2];
    const float* Wv = (const float*)d_in[3];
    const float* Wo = (const float*)d_in[4];
    float* out = (float*)d_out;

    float *Qp, *Kp, *Vp, *Op;
    cudaGetSymbolAddress((void**)&Qp, g_Q);
    cudaGetSymbolAddress((void**)&Kp, g_K);
    cudaGetSymbolAddress((void**)&Vp, g_V);
    cudaGetSymbolAddress((void**)&Op, g_O);

    cudaFuncSetAttribute(attn_kernel,
                         cudaFuncAttributeMaxDynamicSharedMemorySize, SMEM_ATTN);
    cudaFuncSetAttribute(gemm_tf32_kernel,
                         cudaFuncAttributeMaxDynamicSharedMemorySize, SMEM_GEMM);

    // 1. RoPE tables
    {
        int total = Tt * (HDd / 2);
        rope_tables_kernel<<<(total + 255) / 256, 256>>>();
    }
    // 2. Projections (TF32 tensor cores)
    gemm_tf32_kernel<<<dim3(QW / 128, NROW / 128), 256, SMEM_GEMM>>>(x, Wq, Qp, NROW, QW, Dd);
    gemm_tf32_kernel<<<dim3(KW / 128, NROW / 128), 256, SMEM_GEMM>>>(x, Wk, Kp, NROW, KW, Dd);
    gemm_tf32_kernel<<<dim3(KW / 128, NROW / 128), 256, SMEM_GEMM>>>(x, Wv, Vp, NROW, KW, Dd);
    // 3. RoPE on Q and K
    {
        int totalQ = NROW * (QW / 2);
        rope_apply_kernel<<<(totalQ + 255) / 256, 256>>>(Qp, QW / 2, QW);
        int totalK = NROW * (KW / 2);
        rope_apply_kernel<<<(totalK + 255) / 256, 256>>>(Kp, KW / 2, KW);
    }
    // 4. Attention
    attn_kernel<<<dim3(Tt / 64, Bb * Hh), 256, SMEM_ATTN>>>();
    // 5. Output projection (TF32 tensor cores)
    gemm_tf32_kernel<<<dim3(Dd / 128, NROW / 128), 256, SMEM_GEMM>>>(Op, Wo, out, NROW, Dd, Dd);
}

// round 5
// speedup vs baseline: 4.8064x; 3.3045x over previous
#include <cuda_runtime.h>
#include <math.h>

#define Bb   2
#define Tt   2048
#define Dd   2048
#define Hh   16
#define KVh  4
#define HDd  128
#define REP  (Hh / KVh)
#define NROW (Bb * Tt)
#define QW   (Hh * HDd)    // 2048
#define KW   (KVh * HDd)   // 512

// ---- scratch (static device globals; no allocation) ----
__device__ float g_Q[(size_t)NROW * QW];
__device__ float g_K[(size_t)NROW * KW];
__device__ float g_V[(size_t)NROW * KW];
__device__ float g_O[(size_t)NROW * QW];
__device__ float g_cos[Tt * (HDd / 2)];
__device__ float g_sin[Tt * (HDd / 2)];

// ============================================================
// common PTX helpers
// ============================================================
__device__ __forceinline__ unsigned f2tf32(float x) {
    unsigned r;
    asm("cvt.rna.tf32.f32 %0, %1;" : "=r"(r) : "f"(x));
    return r;
}

__device__ __forceinline__ void ldm_x4(unsigned* a, const unsigned* p) {
    unsigned addr = (unsigned)__cvta_generic_to_shared(p);
    asm volatile("ldmatrix.sync.aligned.m8n8.x4.shared.b16 {%0,%1,%2,%3}, [%4];"
        : "=r"(a[0]), "=r"(a[1]), "=r"(a[2]), "=r"(a[3]) : "r"(addr));
}

__device__ __forceinline__ void mma_tf32(float* c, const unsigned* a,
                                         unsigned b0, unsigned b1) {
    asm volatile(
        "mma.sync.aligned.m16n8k8.row.col.f32.tf32.tf32.f32 "
        "{%0,%1,%2,%3}, {%4,%5,%6,%7}, {%8,%9}, {%0,%1,%2,%3};"
        : "+f"(c[0]), "+f"(c[1]), "+f"(c[2]), "+f"(c[3])
        : "r"(a[0]), "r"(a[1]), "r"(a[2]), "r"(a[3]), "r"(b0), "r"(b1));
}

// ============================================================
// RoPE tables (double precision)
// ============================================================
__global__ void rope_tables_kernel() {
    int idx = blockIdx.x * blockDim.x + threadIdx.x;
    if (idx >= Tt * (HDd / 2)) return;
    int i = idx % (HDd / 2);
    int t = idx / (HDd / 2);
    double inv = exp(-((double)(2 * i) / (double)HDd) * log(10000.0));
    double a = (double)t * inv;
    g_cos[idx] = (float)cos(a);
    g_sin[idx] = (float)sin(a);
}

// ============================================================
// TF32 tensor-core GEMM: C[M,N] = A[M,K] @ B[K,N], row-major.
// 128x128x32 block tile, 256 threads = 8 warps, warp tile 32x64.
// ============================================================
#define BM 128
#define BN 128
#define BK 32
#define LDA 36
#define LDB 132
#define ASZ (BM * LDA)
#define BSZ (BK * LDB)
#define SMEM_GEMM ((2 * ASZ + 2 * BSZ) * 4)

__global__ __launch_bounds__(256, 2) void gemm_tf32_kernel(
    const float* __restrict__ A, const float* __restrict__ Bm,
    float* __restrict__ C, int M, int N, int K)
{
    extern __shared__ unsigned smem_u[];
    unsigned* As = smem_u;
    unsigned* Bs = smem_u + 2 * ASZ;

    const int bx = blockIdx.x, by = blockIdx.y;
    const int tid = threadIdx.x;
    const int warp = tid >> 5, lane = tid & 31;
    const int wm = warp & 3;
    const int wn = warp >> 2;

    const int ar = tid >> 3;
    const int ac = (tid & 7) << 2;
    const int br = tid >> 5;
    const int bc = (tid & 31) << 2;

    const float* Ag = A + (size_t)(by * BM) * K;
    const float* Bg = Bm + bx * BN;

    float acc[2][8][4];
#pragma unroll
    for (int mt = 0; mt < 2; mt++)
#pragma unroll
        for (int nt = 0; nt < 8; nt++)
#pragma unroll
            for (int i = 0; i < 4; i++) acc[mt][nt][i] = 0.f;

    float4 av[4], bv[4];

#pragma unroll
    for (int i = 0; i < 4; i++)
        av[i] = *(const float4*)(Ag + (size_t)(ar + 32 * i) * K + ac);
#pragma unroll
    for (int i = 0; i < 4; i++)
        bv[i] = *(const float4*)(Bg + (size_t)(br + 8 * i) * N + bc);
#pragma unroll
    for (int i = 0; i < 4; i++) {
        uint4 u;
        u.x = f2tf32(av[i].x); u.y = f2tf32(av[i].y);
        u.z = f2tf32(av[i].z); u.w = f2tf32(av[i].w);
        *(uint4*)&As[(ar + 32 * i) * LDA + ac] = u;
        uint4 w;
        w.x = f2tf32(bv[i].x); w.y = f2tf32(bv[i].y);
        w.z = f2tf32(bv[i].z); w.w = f2tf32(bv[i].w);
        *(uint4*)&Bs[(br + 8 * i) * LDB + bc] = w;
    }
    __syncthreads();

    int buf = 0;
    for (int k0 = BK; k0 <= K; k0 += BK) {
        if (k0 < K) {
#pragma unroll
            for (int i = 0; i < 4; i++)
                av[i] = *(const float4*)(Ag + (size_t)(ar + 32 * i) * K + k0 + ac);
#pragma unroll
            for (int i = 0; i < 4; i++)
                bv[i] = *(const float4*)(Bg + (size_t)(k0 + br + 8 * i) * N + bc);
        }

        const unsigned* Ab = As + buf * ASZ;
        const unsigned* Bt = Bs + buf * BSZ;
        const int arow = (lane & 7) + ((lane >> 3) & 1) * 8;
        const int acol = (lane >> 4) << 2;
#pragma unroll
        for (int ks = 0; ks < 4; ks++) {
            unsigned afr[2][4];
#pragma unroll
            for (int mt = 0; mt < 2; mt++) {
                int m0 = wm * 32 + mt * 16;
                ldm_x4(afr[mt], Ab + (m0 + arow) * LDA + ks * 8 + acol);
            }
            const unsigned* Bk = Bt + (ks * 8 + (lane & 3)) * LDB + wn * 64 + (lane >> 2);
#pragma unroll
            for (int nt = 0; nt < 8; nt++) {
                unsigned b0 = Bk[nt * 8];
                unsigned b1 = Bk[nt * 8 + 4 * LDB];
                mma_tf32(acc[0][nt], afr[0], b0, b1);
                mma_tf32(acc[1][nt], afr[1], b0, b1);
            }
        }

        if (k0 < K) {
            unsigned* Aw = As + (buf ^ 1) * ASZ;
            unsigned* Bw = Bs + (buf ^ 1) * BSZ;
#pragma unroll
            for (int i = 0; i < 4; i++) {
                uint4 u;
                u.x = f2tf32(av[i].x); u.y = f2tf32(av[i].y);
                u.z = f2tf32(av[i].z); u.w = f2tf32(av[i].w);
                *(uint4*)&Aw[(ar + 32 * i) * LDA + ac] = u;
                uint4 w;
                w.x = f2tf32(bv[i].x); w.y = f2tf32(bv[i].y);
                w.z = f2tf32(bv[i].z); w.w = f2tf32(bv[i].w);
                *(uint4*)&Bw[(br + 8 * i) * LDB + bc] = w;
            }
            __syncthreads();
            buf ^= 1;
        }
    }

    const int g = lane >> 2;
    const int cc = (lane & 3) << 1;
#pragma unroll
    for (int mt = 0; mt < 2; mt++) {
#pragma unroll
        for (int nt = 0; nt < 8; nt++) {
            int row = by * BM + wm * 32 + mt * 16 + g;
            int col = bx * BN + wn * 64 + nt * 8 + cc;
            *(float2*)&C[(size_t)row * N + col] =
                make_float2(acc[mt][nt][0], acc[mt][nt][1]);
            *(float2*)&C[(size_t)(row + 8) * N + col] =
                make_float2(acc[mt][nt][2], acc[mt][nt][3]);
        }
    }
}

// ============================================================
// In-place RoPE.
// ============================================================
__global__ void rope_apply_kernel(float* __restrict__ X, int halfw, int width) {
    int idx = blockIdx.x * blockDim.x + threadIdx.x;
    int total = NROW * halfw;
    if (idx >= total) return;
    int p = idx % halfw;
    int row = idx / halfw;
    int t = row % Tt;
    int i = p & 63;
    int hh = p >> 6;
    int col = hh * HDd + 2 * i;
    float c = g_cos[t * 64 + i];
    float s = g_sin[t * 64 + i];
    float* ptr = X + (size_t)row * width + col;
    float x1 = ptr[0], x2 = ptr[1];
    ptr[0] = x1 * c - x2 * s;
    ptr[1] = x1 * s + x2 * c;
}

// ============================================================
// TF32 tensor-core flash attention, causal, GQA.
// 128 threads = 4 warps; Q tile 64 rows (16/warp), KV tile 64.
// smem: Qs[64][132] tf32 | KV union (K [64][132] / V [64][136]) | Ps[64][68]
// ============================================================
#define LDQ 132
#define LDK 132
#define LDV 136
#define LDP 68
#define SMEM_ATTN ((64 * LDQ + 64 * LDV + 64 * LDP) * 4)   // 86016 B

__global__ __launch_bounds__(128) void attn_mma_kernel() {
    extern __shared__ unsigned smu[];
    unsigned* Qs = smu;
    unsigned* KV = Qs + 64 * LDQ;
    unsigned* Ps = KV + 64 * LDV;

    const int bh = blockIdx.y;
    const int b = bh / Hh;
    const int h = bh % Hh;
    const int kvh = h / REP;
    const int q0 = blockIdx.x * 64;
    const int tid = threadIdx.x, warp = tid >> 5, lane = tid & 31;
    const int g = lane >> 2, qd = lane & 3;
    const int arow = (lane & 7) + ((lane >> 3) & 1) * 8;
    const int acol = (lane >> 4) << 2;
    const float scale = 0.08838834764831845f; // 1/sqrt(128)

    // load Q tile (scale folded in, converted to tf32)
    const float* Qg = g_Q + ((size_t)(b * Tt + q0)) * QW + h * HDd;
    for (int x = tid; x < 64 * 32; x += 128) {
        int r = x >> 5, d4 = (x & 31) << 2;
        float4 q = *(const float4*)(Qg + (size_t)r * QW + d4);
        Qs[r * LDQ + d4 + 0] = f2tf32(q.x * scale);
        Qs[r * LDQ + d4 + 1] = f2tf32(q.y * scale);
        Qs[r * LDQ + d4 + 2] = f2tf32(q.z * scale);
        Qs[r * LDQ + d4 + 3] = f2tf32(q.w * scale);
    }

    float o[16][4];
#pragma unroll
    for (int nt = 0; nt < 16; nt++)
#pragma unroll
        for (int i = 0; i < 4; i++) o[nt][i] = 0.f;
    float m0 = -1e30f, m1 = -1e30f, l0 = 0.f, l1 = 0.f;

    const int ntiles = blockIdx.x + 1;
    for (int tile = 0; tile < ntiles; tile++) {
        const int j0 = tile * 64;
        __syncthreads();   // prev V reads done (and Q stores on iter 0)

        // load K tile -> KV (row-major [j][d], tf32)
        const float* Kg = g_K + ((size_t)(b * Tt + j0)) * KW + kvh * HDd;
        for (int x = tid; x < 64 * 32; x += 128) {
            int j = x >> 5, d4 = (x & 31) << 2;
            float4 kv = *(const float4*)(Kg + (size_t)j * KW + d4);
            KV[j * LDK + d4 + 0] = f2tf32(kv.x);
            KV[j * LDK + d4 + 1] = f2tf32(kv.y);
            KV[j * LDK + d4 + 2] = f2tf32(kv.z);
            KV[j * LDK + d4 + 3] = f2tf32(kv.w);
        }
        __syncthreads();

        // ---- S = (Q*scale) @ K^T : warp rows warp*16..+16, cols 0..63 ----
        float s[8][4];
#pragma unroll
        for (int nt = 0; nt < 8; nt++)
#pragma unroll
            for (int i = 0; i < 4; i++) s[nt][i] = 0.f;

#pragma unroll
        for (int ks = 0; ks < 16; ks++) {
            unsigned afr[4];
            ldm_x4(afr, Qs + (warp * 16 + arow) * LDQ + ks * 8 + acol);
#pragma unroll
            for (int nt = 0; nt < 8; nt++) {
                unsigned b0 = KV[(nt * 8 + g) * LDK + ks * 8 + qd];
                unsigned b1 = KV[(nt * 8 + g) * LDK + ks * 8 + qd + 4];
                mma_tf32(s[nt], afr, b0, b1);
            }
        }

        // causal mask on diagonal tile
        if (j0 == q0) {
            int r0 = warp * 16 + g, r1 = r0 + 8;
#pragma unroll
            for (int nt = 0; nt < 8; nt++) {
                int c = nt * 8 + 2 * qd;
                if (c > r0)     s[nt][0] = -1e30f;
                if (c + 1 > r0) s[nt][1] = -1e30f;
                if (c > r1)     s[nt][2] = -1e30f;
                if (c + 1 > r1) s[nt][3] = -1e30f;
            }
        }

        // ---- online softmax ----
        float mx0 = -1e30f, mx1 = -1e30f;
#pragma unroll
        for (int nt = 0; nt < 8; nt++) {
            mx0 = fmaxf(mx0, fmaxf(s[nt][0], s[nt][1]));
            mx1 = fmaxf(mx1, fmaxf(s[nt][2], s[nt][3]));
        }
        mx0 = fmaxf(mx0, __shfl_xor_sync(0xFFFFFFFFu, mx0, 1));
        mx0 = fmaxf(mx0, __shfl_xor_sync(0xFFFFFFFFu, mx0, 2));
        mx1 = fmaxf(mx1, __shfl_xor_sync(0xFFFFFFFFu, mx1, 1));
        mx1 = fmaxf(mx1, __shfl_xor_sync(0xFFFFFFFFu, mx1, 2));

        float mn0 = fmaxf(m0, mx0), mn1 = fmaxf(m1, mx1);
        float a0 = __expf(m0 - mn0), a1 = __expf(m1 - mn1);
        m0 = mn0; m1 = mn1;

        float ps0 = 0.f, ps1 = 0.f;
        unsigned* Pr0 = Ps + (warp * 16 + g) * LDP;
        unsigned* Pr1 = Pr0 + 8 * LDP;
#pragma unroll
        for (int nt = 0; nt < 8; nt++) {
            float p0 = __expf(s[nt][0] - mn0);
            float p1 = __expf(s[nt][1] - mn0);
            float p2 = __expf(s[nt][2] - mn1);
            float p3 = __expf(s[nt][3] - mn1);
            ps0 += p0 + p1; ps1 += p2 + p3;
            int c = nt * 8 + 2 * qd;
            Pr0[c] = f2tf32(p0); Pr0[c + 1] = f2tf32(p1);
            Pr1[c] = f2tf32(p2); Pr1[c + 1] = f2tf32(p3);
        }
        ps0 += __shfl_xor_sync(0xFFFFFFFFu, ps0, 1);
        ps0 += __shfl_xor_sync(0xFFFFFFFFu, ps0, 2);
        ps1 += __shfl_xor_sync(0xFFFFFFFFu, ps1, 1);
        ps1 += __shfl_xor_sync(0xFFFFFFFFu, ps1, 2);
        l0 = l0 * a0 + ps0;
        l1 = l1 * a1 + ps1;
#pragma unroll
        for (int nt = 0; nt < 16; nt++) {
            o[nt][0] *= a0; o[nt][1] *= a0;
            o[nt][2] *= a1; o[nt][3] *= a1;
        }

        __syncthreads();  // all warps done reading K; Ps visible to all lanes

        // load V tile -> KV (row-major [j][d], stride LDV, tf32)
        const float* Vg = g_V + ((size_t)(b * Tt + j0)) * KW + kvh * HDd;
        for (int x = tid; x < 64 * 32; x += 128) {
            int j = x >> 5, d4 = (x & 31) << 2;
            float4 vv = *(const float4*)(Vg + (size_t)j * KW + d4);
            KV[j * LDV + d4 + 0] = f2tf32(vv.x);
            KV[j * LDV + d4 + 1] = f2tf32(vv.y);
            KV[j * LDV + d4 + 2] = f2tf32(vv.z);
            KV[j * LDV + d4 + 3] = f2tf32(vv.w);
        }
        __syncthreads();

        // ---- O += P @ V ----
#pragma unroll
        for (int ks = 0; ks < 8; ks++) {
            unsigned afr[4];
            ldm_x4(afr, Ps + (warp * 16 + arow) * LDP + ks * 8 + acol);
#pragma unroll
            for (int nt = 0; nt < 16; nt++) {
                unsigned b0 = KV[(ks * 8 + qd) * LDV + nt * 8 + g];
                unsigned b1 = KV[(ks * 8 + qd + 4) * LDV + nt * 8 + g];
                mma_tf32(o[nt], afr, b0, b1);
            }
        }
    }

    // ---- epilogue: normalize, store ----
    float i0 = 1.f / l0, i1 = 1.f / l1;
    float* Og = g_O + ((size_t)(b * Tt + q0 + warp * 16 + g)) * QW + h * HDd;
#pragma unroll
    for (int nt = 0; nt < 16; nt++) {
        int c = nt * 8 + 2 * qd;
        *(float2*)(Og + c) = make_float2(o[nt][0] * i0, o[nt][1] * i0);
        *(float2*)(Og + (size_t)8 * QW + c) = make_float2(o[nt][2] * i1, o[nt][3] * i1);
    }
}

// ============================================================
extern "C" void kernel_launch(void* const* d_in, const int* in_sizes, int n_in,
                              void* d_out, int out_size) {
    (void)in_sizes; (void)n_in; (void)out_size;
    const float* x  = (const float*)d_in[0];
    const float* Wq = (const float*)d_in[1];
    const float* Wk = (const float*)d_in[2];
    const float* Wv = (const float*)d_in[3];
    const float* Wo = (const float*)d_in[4];
    float* out = (float*)d_out;

    float *Qp, *Kp, *Vp, *Op;
    cudaGetSymbolAddress((void**)&Qp, g_Q);
    cudaGetSymbolAddress((void**)&Kp, g_K);
    cudaGetSymbolAddress((void**)&Vp, g_V);
    cudaGetSymbolAddress((void**)&Op, g_O);

    cudaFuncSetAttribute(gemm_tf32_kernel,
                         cudaFuncAttributeMaxDynamicSharedMemorySize, SMEM_GEMM);
    cudaFuncSetAttribute(attn_mma_kernel,
                         cudaFuncAttributeMaxDynamicSharedMemorySize, SMEM_ATTN);

    // 1. RoPE tables
    {
        int total = Tt * (HDd / 2);
        rope_tables_kernel<<<(total + 255) / 256, 256>>>();
    }
    // 2. Projections (TF32 tensor cores)
    gemm_tf32_kernel<<<dim3(QW / 128, NROW / 128), 256, SMEM_GEMM>>>(x, Wq, Qp, NROW, QW, Dd);
    gemm_tf32_kernel<<<dim3(KW / 128, NROW / 128), 256, SMEM_GEMM>>>(x, Wk, Kp, NROW, KW, Dd);
    gemm_tf32_kernel<<<dim3(KW / 128, NROW / 128), 256, SMEM_GEMM>>>(x, Wv, Vp, NROW, KW, Dd);
    // 3. RoPE on Q and K
    {
        int totalQ = NROW * (QW / 2);
        rope_apply_kernel<<<(totalQ + 255) / 256, 256>>>(Qp, QW / 2, QW);
        int totalK = NROW * (KW / 2);
        rope_apply_kernel<<<(totalK + 255) / 256, 256>>>(Kp, KW / 2, KW);
    }
    // 4. Attention (TF32 tensor cores)
    attn_mma_kernel<<<dim3(Tt / 64, Bb * Hh), 128, SMEM_ATTN>>>();
    // 5. Output projection
    gemm_tf32_kernel<<<dim3(Dd / 128, NROW / 128), 256, SMEM_GEMM>>>(Op, Wo, out, NROW, Dd, Dd);
}

// round 6
// speedup vs baseline: 4.9084x; 1.0212x over previous
#include <cuda_runtime.h>
#include <math.h>

#define Bb   2
#define Tt   2048
#define Dd   2048
#define Hh   16
#define KVh  4
#define HDd  128
#define REP  (Hh / KVh)
#define NROW (Bb * Tt)
#define QW   (Hh * HDd)    // 2048
#define KW   (KVh * HDd)   // 512

// ---- scratch (static device globals; no allocation) ----
__device__ float g_Q[(size_t)NROW * QW];
__device__ float g_K[(size_t)NROW * KW];
__device__ float g_V[(size_t)NROW * KW];
__device__ float g_O[(size_t)NROW * QW];
__device__ float g_cos[Tt * (HDd / 2)];
__device__ float g_sin[Tt * (HDd / 2)];

// ============================================================
// common PTX helpers
// ============================================================
__device__ __forceinline__ unsigned f2tf32(float x) {
    unsigned r;
    asm("cvt.rna.tf32.f32 %0, %1;" : "=r"(r) : "f"(x));
    return r;
}

__device__ __forceinline__ void ldm_x4(unsigned* a, const unsigned* p) {
    unsigned addr = (unsigned)__cvta_generic_to_shared(p);
    asm volatile("ldmatrix.sync.aligned.m8n8.x4.shared.b16 {%0,%1,%2,%3}, [%4];"
        : "=r"(a[0]), "=r"(a[1]), "=r"(a[2]), "=r"(a[3]) : "r"(addr));
}

__device__ __forceinline__ void mma_tf32(float* c, const unsigned* a,
                                         unsigned b0, unsigned b1) {
    asm volatile(
        "mma.sync.aligned.m16n8k8.row.col.f32.tf32.tf32.f32 "
        "{%0,%1,%2,%3}, {%4,%5,%6,%7}, {%8,%9}, {%0,%1,%2,%3};"
        : "+f"(c[0]), "+f"(c[1]), "+f"(c[2]), "+f"(c[3])
        : "r"(a[0]), "r"(a[1]), "r"(a[2]), "r"(a[3]), "r"(b0), "r"(b1));
}

// ============================================================
// RoPE tables (double precision)
// ============================================================
__global__ void rope_tables_kernel() {
    int idx = blockIdx.x * blockDim.x + threadIdx.x;
    if (idx >= Tt * (HDd / 2)) return;
    int i = idx % (HDd / 2);
    int t = idx / (HDd / 2);
    double inv = exp(-((double)(2 * i) / (double)HDd) * log(10000.0));
    double a = (double)t * inv;
    g_cos[idx] = (float)cos(a);
    g_sin[idx] = (float)sin(a);
}

// ============================================================
// TF32 tensor-core GEMM with optional dual-output region and
// fused-RoPE epilogue.
//   blockIdx.x <  split_bx : C0 = A @ B0   (local bx = blockIdx.x)
//   blockIdx.x >= split_bx : C1 = A @ B1   (local bx = blockIdx.x - split_bx)
//   RoPE applied in epilogue when blockIdx.x < rope_bx
//     (pairs = adjacent even/odd output cols; t = row % Tt, i = (col%128)/2)
// 128x128x32 block tile, 256 threads = 8 warps, warp tile 32x64.
// ============================================================
#define BM 128
#define BN 128
#define BK 32
#define LDA 36
#define LDB 132
#define ASZ (BM * LDA)
#define BSZ (BK * LDB)
#define SMEM_GEMM ((2 * ASZ + 2 * BSZ) * 4)

__global__ __launch_bounds__(256, 2) void gemm_tf32_kernel(
    const float* __restrict__ A,
    const float* __restrict__ B0, const float* __restrict__ B1,
    float* __restrict__ C0, float* __restrict__ C1,
    int split_bx, int rope_bx, int N, int K)
{
    extern __shared__ unsigned smem_u[];
    unsigned* As = smem_u;
    unsigned* Bs = smem_u + 2 * ASZ;

    const int bxr = blockIdx.x, by = blockIdx.y;
    const float* Bm;
    float* C;
    int bx;
    if (bxr < split_bx) { Bm = B0; C = C0; bx = bxr; }
    else                { Bm = B1; C = C1; bx = bxr - split_bx; }
    const bool rope = (bxr < rope_bx);

    const int tid = threadIdx.x;
    const int warp = tid >> 5, lane = tid & 31;
    const int wm = warp & 3;
    const int wn = warp >> 2;

    const int ar = tid >> 3;
    const int ac = (tid & 7) << 2;
    const int br = tid >> 5;
    const int bc = (tid & 31) << 2;

    const float* Ag = A + (size_t)(by * BM) * K;
    const float* Bg = Bm + bx * BN;

    float acc[2][8][4];
#pragma unroll
    for (int mt = 0; mt < 2; mt++)
#pragma unroll
        for (int nt = 0; nt < 8; nt++)
#pragma unroll
            for (int i = 0; i < 4; i++) acc[mt][nt][i] = 0.f;

    float4 av[4], bv[4];

#pragma unroll
    for (int i = 0; i < 4; i++)
        av[i] = *(const float4*)(Ag + (size_t)(ar + 32 * i) * K + ac);
#pragma unroll
    for (int i = 0; i < 4; i++)
        bv[i] = *(const float4*)(Bg + (size_t)(br + 8 * i) * N + bc);
#pragma unroll
    for (int i = 0; i < 4; i++) {
        uint4 u;
        u.x = f2tf32(av[i].x); u.y = f2tf32(av[i].y);
        u.z = f2tf32(av[i].z); u.w = f2tf32(av[i].w);
        *(uint4*)&As[(ar + 32 * i) * LDA + ac] = u;
        uint4 w;
        w.x = f2tf32(bv[i].x); w.y = f2tf32(bv[i].y);
        w.z = f2tf32(bv[i].z); w.w = f2tf32(bv[i].w);
        *(uint4*)&Bs[(br + 8 * i) * LDB + bc] = w;
    }
    __syncthreads();

    int buf = 0;
    for (int k0 = BK; k0 <= K; k0 += BK) {
        if (k0 < K) {
#pragma unroll
            for (int i = 0; i < 4; i++)
                av[i] = *(const float4*)(Ag + (size_t)(ar + 32 * i) * K + k0 + ac);
#pragma unroll
            for (int i = 0; i < 4; i++)
                bv[i] = *(const float4*)(Bg + (size_t)(k0 + br + 8 * i) * N + bc);
        }

        const unsigned* Ab = As + buf * ASZ;
        const unsigned* Bt = Bs + buf * BSZ;
        const int arow = (lane & 7) + ((lane >> 3) & 1) * 8;
        const int acol = (lane >> 4) << 2;
#pragma unroll
        for (int ks = 0; ks < 4; ks++) {
            unsigned afr[2][4];
#pragma unroll
            for (int mt = 0; mt < 2; mt++) {
                int m0 = wm * 32 + mt * 16;
                ldm_x4(afr[mt], Ab + (m0 + arow) * LDA + ks * 8 + acol);
            }
            const unsigned* Bk = Bt + (ks * 8 + (lane & 3)) * LDB + wn * 64 + (lane >> 2);
#pragma unroll
            for (int nt = 0; nt < 8; nt++) {
                unsigned b0 = Bk[nt * 8];
                unsigned b1 = Bk[nt * 8 + 4 * LDB];
                mma_tf32(acc[0][nt], afr[0], b0, b1);
                mma_tf32(acc[1][nt], afr[1], b0, b1);
            }
        }

        if (k0 < K) {
            unsigned* Aw = As + (buf ^ 1) * ASZ;
            unsigned* Bw = Bs + (buf ^ 1) * BSZ;
#pragma unroll
            for (int i = 0; i < 4; i++) {
                uint4 u;
                u.x = f2tf32(av[i].x); u.y = f2tf32(av[i].y);
                u.z = f2tf32(av[i].z); u.w = f2tf32(av[i].w);
                *(uint4*)&Aw[(ar + 32 * i) * LDA + ac] = u;
                uint4 w;
                w.x = f2tf32(bv[i].x); w.y = f2tf32(bv[i].y);
                w.z = f2tf32(bv[i].z); w.w = f2tf32(bv[i].w);
                *(uint4*)&Bw[(br + 8 * i) * LDB + bc] = w;
            }
            __syncthreads();
            buf ^= 1;
        }
    }

    // ---- epilogue (optional fused RoPE) ----
    const int g = lane >> 2;
    const int cc = (lane & 3) << 1;
#pragma unroll
    for (int mt = 0; mt < 2; mt++) {
#pragma unroll
        for (int nt = 0; nt < 8; nt++) {
            int row = by * BM + wm * 32 + mt * 16 + g;
            int col = bx * BN + wn * 64 + nt * 8 + cc;
            if (rope) {
                int i = (col & (HDd - 1)) >> 1;
                int t0 = row & (Tt - 1);
                float c0 = g_cos[t0 * 64 + i], s0 = g_sin[t0 * 64 + i];
                float x1 = acc[mt][nt][0], x2 = acc[mt][nt][1];
                acc[mt][nt][0] = x1 * c0 - x2 * s0;
                acc[mt][nt][1] = x1 * s0 + x2 * c0;
                int t1 = (row + 8) & (Tt - 1);
                float c1 = g_cos[t1 * 64 + i], s1 = g_sin[t1 * 64 + i];
                x1 = acc[mt][nt][2]; x2 = acc[mt][nt][3];
                acc[mt][nt][2] = x1 * c1 - x2 * s1;
                acc[mt][nt][3] = x1 * s1 + x2 * c1;
            }
            *(float2*)&C[(size_t)row * N + col] =
                make_float2(acc[mt][nt][0], acc[mt][nt][1]);
            *(float2*)&C[(size_t)(row + 8) * N + col] =
                make_float2(acc[mt][nt][2], acc[mt][nt][3]);
        }
    }
}

// ============================================================
// TF32 tensor-core flash attention, causal, GQA.
// 128 threads = 4 warps; Q tile 64 rows (16/warp), KV tile 64.
// QK^T B-fragments via ldmatrix on K[j][d] (one x4 = two n-tiles).
// smem: Qs[64][132] tf32 | KV union (K [64][132] / V [64][136]) | Ps[64][68]
// ============================================================
#define LDQ 132
#define LDK 132
#define LDV 136
#define LDP 68
#define SMEM_ATTN ((64 * LDQ + 64 * LDV + 64 * LDP) * 4)   // 86016 B

__global__ __launch_bounds__(128) void attn_mma_kernel() {
    extern __shared__ unsigned smu[];
    unsigned* Qs = smu;
    unsigned* KV = Qs + 64 * LDQ;
    unsigned* Ps = KV + 64 * LDV;

    const int bh = blockIdx.y;
    const int b = bh / Hh;
    const int h = bh % Hh;
    const int kvh = h / REP;
    const int q0 = blockIdx.x * 64;
    const int tid = threadIdx.x, warp = tid >> 5, lane = tid & 31;
    const int g = lane >> 2, qd = lane & 3;
    const int arow = (lane & 7) + ((lane >> 3) & 1) * 8;
    const int acol = (lane >> 4) << 2;
    const float scale = 0.08838834764831845f; // 1/sqrt(128)

    // load Q tile (scale folded in, converted to tf32)
    const float* Qg = g_Q + ((size_t)(b * Tt + q0)) * QW + h * HDd;
    for (int x = tid; x < 64 * 32; x += 128) {
        int r = x >> 5, d4 = (x & 31) << 2;
        float4 q = *(const float4*)(Qg + (size_t)r * QW + d4);
        Qs[r * LDQ + d4 + 0] = f2tf32(q.x * scale);
        Qs[r * LDQ + d4 + 1] = f2tf32(q.y * scale);
        Qs[r * LDQ + d4 + 2] = f2tf32(q.z * scale);
        Qs[r * LDQ + d4 + 3] = f2tf32(q.w * scale);
    }

    float o[16][4];
#pragma unroll
    for (int nt = 0; nt < 16; nt++)
#pragma unroll
        for (int i = 0; i < 4; i++) o[nt][i] = 0.f;
    float m0 = -1e30f, m1 = -1e30f, l0 = 0.f, l1 = 0.f;

    const int ntiles = blockIdx.x + 1;
    for (int tile = 0; tile < ntiles; tile++) {
        const int j0 = tile * 64;
        __syncthreads();   // prev V reads done (and Q stores on iter 0)

        // load K tile -> KV (row-major [j][d], tf32)
        const float* Kg = g_K + ((size_t)(b * Tt + j0)) * KW + kvh * HDd;
        for (int x = tid; x < 64 * 32; x += 128) {
            int j = x >> 5, d4 = (x & 31) << 2;
            float4 kv = *(const float4*)(Kg + (size_t)j * KW + d4);
            KV[j * LDK + d4 + 0] = f2tf32(kv.x);
            KV[j * LDK + d4 + 1] = f2tf32(kv.y);
            KV[j * LDK + d4 + 2] = f2tf32(kv.z);
            KV[j * LDK + d4 + 3] = f2tf32(kv.w);
        }
        __syncthreads();

        // ---- S = (Q*scale) @ K^T : warp rows warp*16..+16, cols 0..63 ----
        float s[8][4];
#pragma unroll
        for (int nt = 0; nt < 8; nt++)
#pragma unroll
            for (int i = 0; i < 4; i++) s[nt][i] = 0.f;

#pragma unroll
        for (int ks = 0; ks < 16; ks++) {
            unsigned afr[4];
            ldm_x4(afr, Qs + (warp * 16 + arow) * LDQ + ks * 8 + acol);
#pragma unroll
            for (int ntp = 0; ntp < 4; ntp++) {
                unsigned bfr[4];
                ldm_x4(bfr, KV + (ntp * 16 + arow) * LDK + ks * 8 + acol);
                mma_tf32(s[2 * ntp],     afr, bfr[0], bfr[2]);
                mma_tf32(s[2 * ntp + 1], afr, bfr[1], bfr[3]);
            }
        }

        // causal mask on diagonal tile
        if (j0 == q0) {
            int r0 = warp * 16 + g, r1 = r0 + 8;
#pragma unroll
            for (int nt = 0; nt < 8; nt++) {
                int c = nt * 8 + 2 * qd;
                if (c > r0)     s[nt][0] = -1e30f;
                if (c + 1 > r0) s[nt][1] = -1e30f;
                if (c > r1)     s[nt][2] = -1e30f;
                if (c + 1 > r1) s[nt][3] = -1e30f;
            }
        }

        // ---- online softmax ----
        float mx0 = -1e30f, mx1 = -1e30f;
#pragma unroll
        for (int nt = 0; nt < 8; nt++) {
            mx0 = fmaxf(mx0, fmaxf(s[nt][0], s[nt][1]));
            mx1 = fmaxf(mx1, fmaxf(s[nt][2], s[nt][3]));
        }
        mx0 = fmaxf(mx0, __shfl_xor_sync(0xFFFFFFFFu, mx0, 1));
        mx0 = fmaxf(mx0, __shfl_xor_sync(0xFFFFFFFFu, mx0, 2));
        mx1 = fmaxf(mx1, __shfl_xor_sync(0xFFFFFFFFu, mx1, 1));
        mx1 = fmaxf(mx1, __shfl_xor_sync(0xFFFFFFFFu, mx1, 2));

        float mn0 = fmaxf(m0, mx0), mn1 = fmaxf(m1, mx1);
        float a0 = __expf(m0 - mn0), a1 = __expf(m1 - mn1);
        m0 = mn0; m1 = mn1;

        float ps0 = 0.f, ps1 = 0.f;
        unsigned* Pr0 = Ps + (warp * 16 + g) * LDP;
        unsigned* Pr1 = Pr0 + 8 * LDP;
#pragma unroll
        for (int nt = 0; nt < 8; nt++) {
            float p0 = __expf(s[nt][0] - mn0);
            float p1 = __expf(s[nt][1] - mn0);
            float p2 = __expf(s[nt][2] - mn1);
            float p3 = __expf(s[nt][3] - mn1);
            ps0 += p0 + p1; ps1 += p2 + p3;
            int c = nt * 8 + 2 * qd;
            *(uint2*)&Pr0[c] = make_uint2(f2tf32(p0), f2tf32(p1));
            *(uint2*)&Pr1[c] = make_uint2(f2tf32(p2), f2tf32(p3));
        }
        ps0 += __shfl_xor_sync(0xFFFFFFFFu, ps0, 1);
        ps0 += __shfl_xor_sync(0xFFFFFFFFu, ps0, 2);
        ps1 += __shfl_xor_sync(0xFFFFFFFFu, ps1, 1);
        ps1 += __shfl_xor_sync(0xFFFFFFFFu, ps1, 2);
        l0 = l0 * a0 + ps0;
        l1 = l1 * a1 + ps1;
#pragma unroll
        for (int nt = 0; nt < 16; nt++) {
            o[nt][0] *= a0; o[nt][1] *= a0;
            o[nt][2] *= a1; o[nt][3] *= a1;
        }

        __syncthreads();  // all warps done reading K; Ps visible to all lanes

        // load V tile -> KV (row-major [j][d], stride LDV, tf32)
        const float* Vg = g_V + ((size_t)(b * Tt + j0)) * KW + kvh * HDd;
        for (int x = tid; x < 64 * 32; x += 128) {
            int j = x >> 5, d4 = (x & 31) << 2;
            float4 vv = *(const float4*)(Vg + (size_t)j * KW + d4);
            KV[j * LDV + d4 + 0] = f2tf32(vv.x);
            KV[j * LDV + d4 + 1] = f2tf32(vv.y);
            KV[j * LDV + d4 + 2] = f2tf32(vv.z);
            KV[j * LDV + d4 + 3] = f2tf32(vv.w);
        }
        __syncthreads();

        // ---- O += P @ V ----
#pragma unroll
        for (int ks = 0; ks < 8; ks++) {
            unsigned afr[4];
            ldm_x4(afr, Ps + (warp * 16 + arow) * LDP + ks * 8 + acol);
#pragma unroll
            for (int nt = 0; nt < 16; nt++) {
                unsigned b0 = KV[(ks * 8 + qd) * LDV + nt * 8 + g];
                unsigned b1 = KV[(ks * 8 + qd + 4) * LDV + nt * 8 + g];
                mma_tf32(o[nt], afr, b0, b1);
            }
        }
    }

    // ---- epilogue: normalize, store ----
    float i0 = 1.f / l0, i1 = 1.f / l1;
    float* Og = g_O + ((size_t)(b * Tt + q0 + warp * 16 + g)) * QW + h * HDd;
#pragma unroll
    for (int nt = 0; nt < 16; nt++) {
        int c = nt * 8 + 2 * qd;
        *(float2*)(Og + c) = make_float2(o[nt][0] * i0, o[nt][1] * i0);
        *(float2*)(Og + (size_t)8 * QW + c) = make_float2(o[nt][2] * i1, o[nt][3] * i1);
    }
}

// ============================================================
extern "C" void kernel_launch(void* const* d_in, const int* in_sizes, int n_in,
                              void* d_out, int out_size) {
    (void)in_sizes; (void)n_in; (void)out_size;
    const float* x  = (const float*)d_in[0];
    const float* Wq = (const float*)d_in[1];
    const float* Wk = (const float*)d_in[2];
    const float* Wv = (const float*)d_in[3];
    const float* Wo = (const float*)d_in[4];
    float* out = (float*)d_out;

    float *Qp, *Kp, *Vp, *Op;
    cudaGetSymbolAddress((void**)&Qp, g_Q);
    cudaGetSymbolAddress((void**)&Kp, g_K);
    cudaGetSymbolAddress((void**)&Vp, g_V);
    cudaGetSymbolAddress((void**)&Op, g_O);

    cudaFuncSetAttribute(gemm_tf32_kernel,
                         cudaFuncAttributeMaxDynamicSharedMemorySize, SMEM_GEMM);
    cudaFuncSetAttribute(attn_mma_kernel,
                         cudaFuncAttributeMaxDynamicSharedMemorySize, SMEM_ATTN);

    // 1. RoPE tables (needed by GEMM epilogues)
    {
        int total = Tt * (HDd / 2);
        rope_tables_kernel<<<(total + 255) / 256, 256>>>();
    }
    // 2. Q projection with fused RoPE
    gemm_tf32_kernel<<<dim3(QW / 128, NROW / 128), 256, SMEM_GEMM>>>(
        x, Wq, Wq, Qp, Qp, /*split_bx=*/QW / 128, /*rope_bx=*/QW / 128, QW, Dd);
    // 3. Fused K+V projection (K half gets RoPE), 256 CTAs
    gemm_tf32_kernel<<<dim3(2 * KW / 128, NROW / 128), 256, SMEM_GEMM>>>(
        x, Wk, Wv, Kp, Vp, /*split_bx=*/KW / 128, /*rope_bx=*/KW / 128, KW, Dd);
    // 4. Attention (TF32 tensor cores)
    attn_mma_kernel<<<dim3(Tt / 64, Bb * Hh), 128, SMEM_ATTN>>>();
    // 5. Output projection (no RoPE)
    gemm_tf32_kernel<<<dim3(Dd / 128, NROW / 128), 256, SMEM_GEMM>>>(
        Op, Wo, Wo, out, out, /*split_bx=*/Dd / 128, /*rope_bx=*/0, Dd, Dd);
}